// round 14
// baseline (speedup 1.0000x reference)
#include <cuda_runtime.h>
#include <cuda_fp16.h>
#include <cstdint>

#define N_NODES 100000
#define N_EDGES 3200000
#define IN_F    256
#define OUT_F   128
#define SCAN_NB ((N_NODES + 1023) / 1024)   // 98

// -------- device scratch (no allocs allowed) --------
__device__ __half g_support[(size_t)N_NODES * OUT_F];  // X @ W in fp16
__device__ unsigned int g_edges[N_EDGES];              // packed (val15 << 17 | col17), grouped by row
__device__ int   g_rank[N_EDGES];                      // edge rank within its row
__device__ int   g_deg[N_NODES];
__device__ int   g_offset[N_NODES + 1];
__device__ int   g_blk[128];                           // lookback state: (sum<<2)|status
// W in fp16, transposed to [n][k] (k contiguous) for mma B-col fragments
__device__ __align__(16) __half g_Bh[OUT_F * IN_F];

// ---------------------------------------------------------------------------
// W -> fp16, transposed [n][k]
// ---------------------------------------------------------------------------
__global__ void wconv_kernel(const float* __restrict__ W,
                             __half* __restrict__ Bh)
{
    int idx = blockIdx.x * blockDim.x + threadIdx.x;   // k*128 + n
    if (idx >= IN_F * OUT_F) return;
    int k = idx >> 7;
    int n = idx & 127;
    Bh[n * IN_F + k] = __float2half_rn(W[idx]);
}

// ---------------------------------------------------------------------------
// fp16 GEMM via mma.sync m16n8k16 (f32 accum); fp16 output for the gather
// ---------------------------------------------------------------------------
#define ASTRIDE 72          // padded row stride (elements) for A/B smem tiles

__device__ __forceinline__ void mma_f16(float* c, const uint32_t* a, const uint32_t* b)
{
    asm volatile(
        "mma.sync.aligned.m16n8k16.row.col.f32.f16.f16.f32 "
        "{%0,%1,%2,%3}, {%4,%5,%6,%7}, {%8,%9}, {%0,%1,%2,%3};\n"
        : "+f"(c[0]), "+f"(c[1]), "+f"(c[2]), "+f"(c[3])
        : "r"(a[0]), "r"(a[1]), "r"(a[2]), "r"(a[3]), "r"(b[0]), "r"(b[1]));
}

__global__ __launch_bounds__(256) void gemm_mma_kernel(
    const float* __restrict__ X,
    const __half* __restrict__ Bhg,
    __half* __restrict__ S)
{
    __shared__ __align__(16) __half Ah[128 * ASTRIDE];
    __shared__ __align__(16) __half Bh[128 * ASTRIDE];

    const int tid  = threadIdx.x;
    const int wid  = tid >> 5;
    const int lane = tid & 31;
    const int g    = lane >> 2;
    const int tig  = lane & 3;
    const int row0 = blockIdx.x * 128;

    const int mrow0 = (wid & 3) * 32;
    const int ncol0 = (wid >> 2) * 64;

    float acc[2][8][4];
#pragma unroll
    for (int mi = 0; mi < 2; ++mi)
#pragma unroll
        for (int ni = 0; ni < 8; ++ni)
#pragma unroll
            for (int r = 0; r < 4; ++r) acc[mi][ni][r] = 0.f;

    for (int k0 = 0; k0 < IN_F; k0 += 64) {
        if (k0) __syncthreads();

#pragma unroll
        for (int i = 0; i < 8; ++i) {
            int idx = tid + i * 256;
            int row = idx >> 4;
            int c4  = (idx & 15) * 4;
            float4 v = make_float4(0.f, 0.f, 0.f, 0.f);
            int grow = row0 + row;
            if (grow < N_NODES)
                v = *(const float4*)&X[(size_t)grow * IN_F + k0 + c4];
            int off = row * ASTRIDE + c4;
            *(__half2*)&Ah[off]     = __floats2half2_rn(v.x, v.y);
            *(__half2*)&Ah[off + 2] = __floats2half2_rn(v.z, v.w);
        }
#pragma unroll
        for (int i = 0; i < 4; ++i) {
            int idx = tid + i * 256;
            int n   = idx >> 3;
            int k8  = (idx & 7) * 8;
            uint4 vh = *(const uint4*)&Bhg[n * IN_F + k0 + k8];
            *(uint4*)&Bh[n * ASTRIDE + k8] = vh;
        }
        __syncthreads();

#pragma unroll
        for (int kk = 0; kk < 4; ++kk) {
            const int kb = kk * 16;
            uint32_t ah[2][4];
#pragma unroll
            for (int mi = 0; mi < 2; ++mi) {
                int ra = (mrow0 + mi * 16 + g) * ASTRIDE + kb + 2 * tig;
                int rb = ra + 8 * ASTRIDE;
                ah[mi][0] = *(const uint32_t*)&Ah[ra];
                ah[mi][1] = *(const uint32_t*)&Ah[rb];
                ah[mi][2] = *(const uint32_t*)&Ah[ra + 8];
                ah[mi][3] = *(const uint32_t*)&Ah[rb + 8];
            }
#pragma unroll
            for (int ni = 0; ni < 8; ++ni) {
                int cb = (ncol0 + ni * 8 + g) * ASTRIDE + kb + 2 * tig;
                uint32_t bh[2];
                bh[0] = *(const uint32_t*)&Bh[cb];
                bh[1] = *(const uint32_t*)&Bh[cb + 8];
#pragma unroll
                for (int mi = 0; mi < 2; ++mi)
                    mma_f16(acc[mi][ni], ah[mi], bh);
            }
        }
    }

#pragma unroll
    for (int mi = 0; mi < 2; ++mi) {
        int r0 = row0 + mrow0 + mi * 16 + g;
        int r1 = r0 + 8;
#pragma unroll
        for (int ni = 0; ni < 8; ++ni) {
            int col = ncol0 + ni * 8 + tig * 2;
            if (r0 < N_NODES)
                *(__half2*)&S[(size_t)r0 * OUT_F + col] =
                    __floats2half2_rn(acc[mi][ni][0], acc[mi][ni][1]);
            if (r1 < N_NODES)
                *(__half2*)&S[(size_t)r1 * OUT_F + col] =
                    __floats2half2_rn(acc[mi][ni][2], acc[mi][ni][3]);
        }
    }
}

// ---------------------------------------------------------------------------
// CSR build: zero -> hist(+rank) -> fused lookback scan -> atomic-free scatter
// ---------------------------------------------------------------------------
__global__ void zero_kernel(int* __restrict__ deg, int* __restrict__ blk)
{
    int i = blockIdx.x * blockDim.x + threadIdx.x;
    if (i < N_NODES) deg[i] = 0;
    if (i < 128) blk[i] = 0;
}

__global__ void hist_kernel(const int* __restrict__ erow, int* __restrict__ deg,
                            int* __restrict__ rank)
{
    int e = blockIdx.x * blockDim.x + threadIdx.x;
    if (e < N_EDGES) rank[e] = atomicAdd(&deg[erow[e]], 1);
}

// Single-kernel exclusive scan over deg -> offset (decoupled lookback).
__global__ __launch_bounds__(1024) void scan_fused_kernel(
    const int* __restrict__ deg, int* __restrict__ offset, int* __restrict__ blk)
{
    __shared__ int buf[2][1024];
    __shared__ int base_sh;
    const int t   = threadIdx.x;
    const int bid = blockIdx.x;
    const int i   = bid * 1024 + t;
    const int v   = (i < N_NODES) ? deg[i] : 0;
    buf[0][t] = v;
    __syncthreads();
    int src = 0;
#pragma unroll
    for (int d = 1; d < 1024; d <<= 1) {
        int nv = buf[src][t] + (t >= d ? buf[src][t - d] : 0);
        buf[src ^ 1][t] = nv;
        src ^= 1;
        __syncthreads();
    }
    const int incl  = buf[src][t];
    const int total = buf[src][1023];

    if (t == 0) {
        if (bid == 0) {
            atomicExch(&blk[0], (total << 2) | 2);
            base_sh = 0;
        } else {
            atomicExch(&blk[bid], (total << 2) | 1);
            int base = 0;
            int p = bid - 1;
            while (true) {
                int s = atomicAdd(&blk[p], 0);
                int st = s & 3;
                if (st == 0) continue;
                base += s >> 2;
                if (st == 2) break;
                --p;
            }
            atomicExch(&blk[bid], ((base + total) << 2) | 2);
            base_sh = base;
        }
    }
    __syncthreads();
    const int base = base_sh;
    if (i < N_NODES) offset[i] = base + incl - v;
    if (bid == 0 && t == 0) offset[N_NODES] = N_EDGES;
}

// Atomic-free scatter; packs (col, fp16 val sans sign bit) into 4 bytes.
__global__ void scatter_kernel(
    const int* __restrict__ erow, const int* __restrict__ ecol,
    const float* __restrict__ eval, const int* __restrict__ offset,
    const int* __restrict__ rank, unsigned int* __restrict__ edges)
{
    int e = blockIdx.x * blockDim.x + threadIdx.x;
    if (e >= N_EDGES) return;
    int pos = offset[erow[e]] + rank[e];
    unsigned int hb = (unsigned int)__half_as_ushort(__float2half_rn(eval[e]));
    edges[pos] = (hb << 17) | (unsigned int)ecol[e];
}

// ---------------------------------------------------------------------------
// Gather: warp per node; 2 edges per iteration (half-warp each, LDG.128);
// cross-half shfl reduction; fused bias + ReLU.
// ---------------------------------------------------------------------------
__global__ __launch_bounds__(256) void gather_kernel(
    const int* __restrict__ offset, const unsigned int* __restrict__ edges,
    const __half* __restrict__ S, const float* __restrict__ bias,
    float* __restrict__ out)
{
    const int warp = threadIdx.x >> 5;
    const int lane = threadIdx.x & 31;
    const int half = lane >> 4;        // which edge of the pair
    const int li   = lane & 15;        // owns feats li*8 .. li*8+7
    const int n    = blockIdx.x * 8 + warp;
    if (n >= N_NODES) return;

    const int start = __ldg(&offset[n]);
    const int end   = __ldg(&offset[n + 1]);

    float4 a0 = make_float4(0.f, 0.f, 0.f, 0.f);
    float4 a1 = make_float4(0.f, 0.f, 0.f, 0.f);

    int e0 = start;
    for (; e0 + 32 <= end; e0 += 32) {
        unsigned int ed = __ldg(&edges[e0 + lane]);
#pragma unroll
        for (int j = 0; j < 16; ++j) {
            unsigned int p = __shfl_sync(0xffffffffu, ed, 2 * j + half);
            int   c = (int)(p & 0x1FFFFu);
            float v = __half2float(__ushort_as_half((unsigned short)(p >> 17)));
            uint4 sv = *(const uint4*)&S[(size_t)c * OUT_F + li * 8];
            float2 f0 = __half22float2(*(__half2*)&sv.x);
            float2 f1 = __half22float2(*(__half2*)&sv.y);
            float2 f2 = __half22float2(*(__half2*)&sv.z);
            float2 f3 = __half22float2(*(__half2*)&sv.w);
            a0.x += f0.x * v; a0.y += f0.y * v; a0.z += f1.x * v; a0.w += f1.y * v;
            a1.x += f2.x * v; a1.y += f2.y * v; a1.z += f3.x * v; a1.w += f3.y * v;
        }
    }
    // tail: cnt < 32 edges; out-of-range lanes hold ed=0 -> v=0 (row-0 read harmless)
    {
        int cnt = end - e0;
        int idx = e0 + lane;
        unsigned int ed = (idx < end) ? __ldg(&edges[idx]) : 0u;
        for (int j = 0; 2 * j < cnt; ++j) {
            unsigned int p = __shfl_sync(0xffffffffu, ed, 2 * j + half);
            int   c = (int)(p & 0x1FFFFu);
            float v = __half2float(__ushort_as_half((unsigned short)(p >> 17)));
            uint4 sv = *(const uint4*)&S[(size_t)c * OUT_F + li * 8];
            float2 f0 = __half22float2(*(__half2*)&sv.x);
            float2 f1 = __half22float2(*(__half2*)&sv.y);
            float2 f2 = __half22float2(*(__half2*)&sv.z);
            float2 f3 = __half22float2(*(__half2*)&sv.w);
            a0.x += f0.x * v; a0.y += f0.y * v; a0.z += f1.x * v; a0.w += f1.y * v;
            a1.x += f2.x * v; a1.y += f2.y * v; a1.z += f3.x * v; a1.w += f3.y * v;
        }
    }

    // cross-half reduction: even-edge partials (lanes 0-15) + odd-edge partials (16-31)
    a0.x += __shfl_xor_sync(0xffffffffu, a0.x, 16);
    a0.y += __shfl_xor_sync(0xffffffffu, a0.y, 16);
    a0.z += __shfl_xor_sync(0xffffffffu, a0.z, 16);
    a0.w += __shfl_xor_sync(0xffffffffu, a0.w, 16);
    a1.x += __shfl_xor_sync(0xffffffffu, a1.x, 16);
    a1.y += __shfl_xor_sync(0xffffffffu, a1.y, 16);
    a1.z += __shfl_xor_sync(0xffffffffu, a1.z, 16);
    a1.w += __shfl_xor_sync(0xffffffffu, a1.w, 16);

    if (half == 0) {
        const float4 b0 = *(const float4*)&bias[li * 8];
        const float4 b1 = *(const float4*)&bias[li * 8 + 4];
        float4 o0, o1;
        o0.x = fmaxf(a0.x + b0.x, 0.f);
        o0.y = fmaxf(a0.y + b0.y, 0.f);
        o0.z = fmaxf(a0.z + b0.z, 0.f);
        o0.w = fmaxf(a0.w + b0.w, 0.f);
        o1.x = fmaxf(a1.x + b1.x, 0.f);
        o1.y = fmaxf(a1.y + b1.y, 0.f);
        o1.z = fmaxf(a1.z + b1.z, 0.f);
        o1.w = fmaxf(a1.w + b1.w, 0.f);
        float* dst = &out[(size_t)n * OUT_F + li * 8];
        *(float4*)dst       = o0;
        *(float4*)(dst + 4) = o1;
    }
}

// ---------------------------------------------------------------------------
// Inputs (metadata order): x, edge_row, edge_col, edge_val, weight, bias
// GEMM chain forked onto a side stream; CSR build on main stream; join at gather.
// ---------------------------------------------------------------------------
extern "C" void kernel_launch(void* const* d_in, const int* in_sizes, int n_in,
                              void* d_out, int out_size)
{
    const float* x     = (const float*)d_in[0];
    const int*   erow  = (const int*)  d_in[1];
    const int*   ecol  = (const int*)  d_in[2];
    const float* eval_ = (const float*)d_in[3];
    const float* w     = (const float*)d_in[4];
    const float* bias  = (const float*)d_in[5];
    float*       out   = (float*)d_out;

    __half* support;     cudaGetSymbolAddress((void**)&support, g_support);
    unsigned int* edges; cudaGetSymbolAddress((void**)&edges,   g_edges);
    int*   rank;         cudaGetSymbolAddress((void**)&rank,    g_rank);
    int*   deg;          cudaGetSymbolAddress((void**)&deg,     g_deg);
    int*   offset;       cudaGetSymbolAddress((void**)&offset,  g_offset);
    int*   blk;          cudaGetSymbolAddress((void**)&blk,     g_blk);
    __half* bh;          cudaGetSymbolAddress((void**)&bh,      g_Bh);

    cudaStream_t s2;
    cudaEvent_t  eFork, eJoin;
    cudaStreamCreateWithFlags(&s2, cudaStreamNonBlocking);
    cudaEventCreateWithFlags(&eFork, cudaEventDisableTiming);
    cudaEventCreateWithFlags(&eJoin, cudaEventDisableTiming);

    // ---- fork: GEMM chain on s2 ----
    cudaEventRecord(eFork, 0);
    cudaStreamWaitEvent(s2, eFork, 0);
    wconv_kernel<<<(IN_F * OUT_F + 255) / 256, 256, 0, s2>>>(w, bh);
    gemm_mma_kernel<<<(N_NODES + 127) / 128, 256, 0, s2>>>(x, bh, support);
    cudaEventRecord(eJoin, s2);

    // ---- CSR build on the main (capture) stream ----
    zero_kernel<<<(N_NODES + 255) / 256, 256>>>(deg, blk);
    hist_kernel<<<(N_EDGES + 255) / 256, 256>>>(erow, deg, rank);
    scan_fused_kernel<<<SCAN_NB, 1024>>>(deg, offset, blk);
    scatter_kernel<<<(N_EDGES + 255) / 256, 256>>>(erow, ecol, eval_, offset, rank, edges);

    // ---- join, then gather ----
    cudaStreamWaitEvent(0, eJoin, 0);
    gather_kernel<<<(N_NODES + 7) / 8, 256>>>(offset, edges, support, bias, out);

    cudaEventDestroy(eFork);
    cudaEventDestroy(eJoin);
    cudaStreamDestroy(s2);
}